// round 13
// baseline (speedup 1.0000x reference)
#include <cuda_runtime.h>
#include <cuda_bf16.h>
#include <math.h>
#include <stdint.h>

// Problem dims (fixed by the dataset)
#define BATCH 1024
#define SEQ   512
#define DIM   768

#define NCHUNK 4
#define CHUNK_B (BATCH / NCHUNK)   // 256 batches per pool chunk

// ---------------------------------------------------------------------------
// Scratch (allocation-free rule: __device__ globals)
// ---------------------------------------------------------------------------
__device__ uint32_t g_pool_hi[BATCH * DIM / 2];
__device__ uint32_t g_pool_lo[BATCH * DIM / 2];
__device__ uint32_t g_hid_hi[BATCH * DIM / 2];
__device__ uint32_t g_hid_lo[BATCH * DIM / 2];
__device__ __nv_bfloat16 g_w1t_hi[DIM * DIM];   // [N][K]
__device__ __nv_bfloat16 g_w1t_lo[DIM * DIM];
__device__ __nv_bfloat16 g_w2t_hi[DIM * DIM];
__device__ __nv_bfloat16 g_w2t_lo[DIM * DIM];

__device__ __forceinline__ void split1(float x, float& h, float& l)
{
    __nv_bfloat16 hb = __float2bfloat16(x);
    h = __bfloat162float(hb);
    l = x - h;
}

__device__ __forceinline__ uint32_t pack_bf2(float a, float b)
{
    __nv_bfloat162 t = __floats2bfloat162_rn(a, b);   // .x = a (low 16 bits)
    return *reinterpret_cast<uint32_t*>(&t);
}

__device__ __forceinline__ float2 ldcs_f2(const float2* p)
{
    float2 v;
    asm volatile("ld.global.cs.v2.f32 {%0,%1}, [%2];"
                 : "=f"(v.x), "=f"(v.y) : "l"(p));
    return v;
}

// ---------------------------------------------------------------------------
// Kernel 1: masked sum pooling chunk (256 batches) -> bf16 hi/lo
// ---------------------------------------------------------------------------
__global__ __launch_bounds__(384) void pool_kernel(
    const float* __restrict__ x,      // [BATCH, SEQ, DIM]
    const int*   __restrict__ mask,   // [BATCH, SEQ]
    int b_base)
{
    __shared__ int s_idx[SEQ];
    __shared__ int s_cnt;

    const int b   = b_base + blockIdx.x;
    const int tid = threadIdx.x;

    if (tid == 0) s_cnt = 0;
    __syncthreads();

    const int* mrow = mask + (size_t)b * SEQ;
    for (int s = tid; s < SEQ; s += 384) {
        if (mrow[s] != 0) {
            int p = atomicAdd(&s_cnt, 1);
            s_idx[p] = s;
        }
    }
    __syncthreads();

    const int cnt = s_cnt;
    const float2* base = reinterpret_cast<const float2*>(x + (size_t)b * SEQ * DIM);
    const int rs2 = DIM / 2;

    float2 acc; acc.x = 0.f; acc.y = 0.f;

    int i = 0;
    for (; i + 4 <= cnt; i += 4) {
        int s0 = s_idx[i + 0];
        int s1 = s_idx[i + 1];
        int s2 = s_idx[i + 2];
        int s3 = s_idx[i + 3];
        float2 v0 = ldcs_f2(base + (size_t)s0 * rs2 + tid);
        float2 v1 = ldcs_f2(base + (size_t)s1 * rs2 + tid);
        float2 v2 = ldcs_f2(base + (size_t)s2 * rs2 + tid);
        float2 v3 = ldcs_f2(base + (size_t)s3 * rs2 + tid);
        acc.x += (v0.x + v1.x) + (v2.x + v3.x);
        acc.y += (v0.y + v1.y) + (v2.y + v3.y);
    }
    for (; i < cnt; i++) {
        float2 v = ldcs_f2(base + (size_t)s_idx[i] * rs2 + tid);
        acc.x += v.x;
        acc.y += v.y;
    }

    float hx, lx, hy, ly;
    split1(acc.x, hx, lx);
    split1(acc.y, hy, ly);
    g_pool_hi[(size_t)b * rs2 + tid] = pack_bf2(hx, hy);
    g_pool_lo[(size_t)b * rs2 + tid] = pack_bf2(lx, ly);
}

// ---------------------------------------------------------------------------
// Kernel 1b: W [K][N] fp32 -> Wt [N][K] bf16 hi/lo (tiled transpose)
// grid (24, 24, 2), block (32, 8)
// ---------------------------------------------------------------------------
__global__ __launch_bounds__(256) void convert_w_kernel(
    const float* __restrict__ W1, const float* __restrict__ W2)
{
    __shared__ float t[32][33];
    const float* W = blockIdx.z ? W2 : W1;
    __nv_bfloat16* Oh = blockIdx.z ? g_w2t_hi : g_w1t_hi;
    __nv_bfloat16* Ol = blockIdx.z ? g_w2t_lo : g_w1t_lo;

    const int n0 = blockIdx.x * 32;
    const int k0 = blockIdx.y * 32;
    const int tx = threadIdx.x;
    const int ty = threadIdx.y;

#pragma unroll
    for (int i = 0; i < 4; i++)
        t[ty + 8 * i][tx] = W[(size_t)(k0 + ty + 8 * i) * DIM + n0 + tx];
    __syncthreads();

#pragma unroll
    for (int i = 0; i < 4; i++) {
        int r = ty + 8 * i;                 // local n
        float v = t[tx][r];                 // = W[k0+tx][n0+r]
        float h, l;
        split1(v, h, l);
        size_t o = (size_t)(n0 + r) * DIM + k0 + tx;
        Oh[o] = __float2bfloat16(h);
        Ol[o] = __float2bfloat16(l);
    }
}

// ---------------------------------------------------------------------------
// Kernel 2 (R9, measured 26.6us full-size): C = tanh(A @ B^T + bias);
// A [M][K], B [N][K] bf16 hi/lo; 3-term split HH+HL+LH; cp.async 3-stage;
// BM=BN=64, BK=32; 128 threads (2x2 warps). m_base selects the batch chunk.
// ---------------------------------------------------------------------------
#define SROW 80
#define TILE_B (64 * SROW)            // 5120 B per operand tile
#define STAGE_B (4 * TILE_B)          // 20480 B
#define NSTAGES 3
#define GEMM_SMEM (NSTAGES * STAGE_B) // 61440 B
#define OFF_AH 0
#define OFF_AL TILE_B
#define OFF_BH (2 * TILE_B)
#define OFF_BL (3 * TILE_B)

__device__ __forceinline__ void cp16(uint32_t dst, const void* src)
{
    asm volatile("cp.async.cg.shared.global [%0], [%1], 16;"
                 :: "r"(dst), "l"(src));
}
#define CP_COMMIT() asm volatile("cp.async.commit_group;" ::: "memory")
#define CP_WAIT2()  asm volatile("cp.async.wait_group 2;" ::: "memory")

__device__ __forceinline__ void mma_bf16(
    float c[4], uint32_t a0, uint32_t a1, uint32_t a2, uint32_t a3,
    uint32_t b0, uint32_t b1)
{
    asm volatile(
        "mma.sync.aligned.m16n8k16.row.col.f32.bf16.bf16.f32 "
        "{%0,%1,%2,%3}, {%4,%5,%6,%7}, {%8,%9}, {%0,%1,%2,%3};\n"
        : "+f"(c[0]), "+f"(c[1]), "+f"(c[2]), "+f"(c[3])
        : "r"(a0), "r"(a1), "r"(a2), "r"(a3), "r"(b0), "r"(b1));
}

template <bool SPLIT_OUT>
__global__ __launch_bounds__(128) void gemm_pipe(
    const __nv_bfloat16* __restrict__ Ah,  // [M][K]
    const __nv_bfloat16* __restrict__ Al,
    const __nv_bfloat16* __restrict__ Bh,  // [N][K]
    const __nv_bfloat16* __restrict__ Bl,
    const float* __restrict__ bias,
    float* __restrict__ Cf,                 // if !SPLIT_OUT
    uint32_t* __restrict__ Chh,             // if SPLIT_OUT
    uint32_t* __restrict__ Chl,
    int m_base, int N, int K)
{
    extern __shared__ char dyn[];
    const uint32_t sbase = (uint32_t)__cvta_generic_to_shared(dyn);

    const int tid  = threadIdx.x;
    const int lane = tid & 31;
    const int warp = tid >> 5;       // 0..3
    const int gid  = lane >> 2;      // 0..7
    const int tig  = lane & 3;       // 0..3
    const int warpM = (warp & 1) * 32;
    const int warpN = (warp >> 1) * 32;

    const int m0 = m_base + blockIdx.y * 64;
    const int n0 = blockIdx.x * 64;

    const int r0 = tid >> 2;          // 0..31
    const int q0 = tid & 3;           // 16B col group

    float acc[2][4][4];
#pragma unroll
    for (int mt = 0; mt < 2; mt++)
#pragma unroll
        for (int nt = 0; nt < 4; nt++)
#pragma unroll
            for (int r = 0; r < 4; r++)
                acc[mt][nt][r] = 0.f;

#define ISSUE(k0v, st)                                                         \
    do {                                                                       \
        uint32_t sb = sbase + (st) * STAGE_B;                                  \
        _Pragma("unroll")                                                      \
        for (int l = 0; l < 2; l++) {                                          \
            int row = r0 + 32 * l;                                             \
            uint32_t d = sb + row * SROW + q0 * 16;                            \
            size_t ga = (size_t)(m0 + row) * K + (k0v) + q0 * 8;               \
            size_t gb = (size_t)(n0 + row) * K + (k0v) + q0 * 8;               \
            cp16(d + OFF_AH, Ah + ga);                                         \
            cp16(d + OFF_AL, Al + ga);                                         \
            cp16(d + OFF_BH, Bh + gb);                                         \
            cp16(d + OFF_BL, Bl + gb);                                         \
        }                                                                      \
        CP_COMMIT();                                                           \
    } while (0)

#define LD32(off) (*reinterpret_cast<const uint32_t*>(dyn + (off)))

    ISSUE(0, 0);
    ISSUE(32, 1);
    ISSUE(64, 2);

    const int NIT = K / 32;   // 24
    for (int t = 0; t < NIT; t++) {
        CP_WAIT2();
        __syncthreads();

        const uint32_t sb = (uint32_t)((t % NSTAGES) * STAGE_B);
#pragma unroll
        for (int ks = 0; ks < 2; ks++) {
            const int kb = ks * 8;

            uint32_t ah[2][4], al[2][4];
#pragma unroll
            for (int mt = 0; mt < 2; mt++) {
                const int rm = warpM + mt * 16 + gid;
                uint32_t b0 = sb + rm * SROW + (kb + tig) * 4;
                uint32_t b8 = sb + (rm + 8) * SROW + (kb + tig) * 4;
                ah[mt][0] = LD32(b0 + OFF_AH);
                ah[mt][1] = LD32(b8 + OFF_AH);
                ah[mt][2] = LD32(b0 + OFF_AH + 16);
                ah[mt][3] = LD32(b8 + OFF_AH + 16);
                al[mt][0] = LD32(b0 + OFF_AL);
                al[mt][1] = LD32(b8 + OFF_AL);
                al[mt][2] = LD32(b0 + OFF_AL + 16);
                al[mt][3] = LD32(b8 + OFF_AL + 16);
            }
            uint32_t bh[4][2], bl[4][2];
#pragma unroll
            for (int nt = 0; nt < 4; nt++) {
                const int nn = warpN + nt * 8 + gid;
                uint32_t b0 = sb + nn * SROW + (kb + tig) * 4;
                bh[nt][0] = LD32(b0 + OFF_BH);
                bh[nt][1] = LD32(b0 + OFF_BH + 16);
                bl[nt][0] = LD32(b0 + OFF_BL);
                bl[nt][1] = LD32(b0 + OFF_BL + 16);
            }

#pragma unroll
            for (int mt = 0; mt < 2; mt++)
#pragma unroll
                for (int nt = 0; nt < 4; nt++) {
                    mma_bf16(acc[mt][nt], ah[mt][0], ah[mt][1], ah[mt][2], ah[mt][3],
                             bh[nt][0], bh[nt][1]);
                    mma_bf16(acc[mt][nt], ah[mt][0], ah[mt][1], ah[mt][2], ah[mt][3],
                             bl[nt][0], bl[nt][1]);
                    mma_bf16(acc[mt][nt], al[mt][0], al[mt][1], al[mt][2], al[mt][3],
                             bh[nt][0], bh[nt][1]);
                }
        }
        __syncthreads();

        if (t + NSTAGES < NIT) {
            ISSUE((t + NSTAGES) * 32, t % NSTAGES);
        } else {
            CP_COMMIT();
        }
    }

    // Epilogue: bias + tanh
#pragma unroll
    for (int mt = 0; mt < 2; mt++) {
#pragma unroll
        for (int nt = 0; nt < 4; nt++) {
            const int row = m0 + warpM + mt * 16 + gid;
            const int col = n0 + warpN + nt * 8 + tig * 2;
            float2 bv = *reinterpret_cast<const float2*>(bias + col);
            float o0 = tanhf(acc[mt][nt][0] + bv.x);
            float o1 = tanhf(acc[mt][nt][1] + bv.y);
            float o2 = tanhf(acc[mt][nt][2] + bv.x);
            float o3 = tanhf(acc[mt][nt][3] + bv.y);
            if (SPLIT_OUT) {
                float h0, l0, h1, l1;
                split1(o0, h0, l0);
                split1(o1, h1, l1);
                size_t idx = ((size_t)row * N + col) >> 1;
                Chh[idx] = pack_bf2(h0, h1);
                Chl[idx] = pack_bf2(l0, l1);
                split1(o2, h0, l0);
                split1(o3, h1, l1);
                size_t idx2 = ((size_t)(row + 8) * N + col) >> 1;
                Chh[idx2] = pack_bf2(h0, h1);
                Chl[idx2] = pack_bf2(l0, l1);
            } else {
                float2 w0; w0.x = o0; w0.y = o1;
                *reinterpret_cast<float2*>(Cf + (size_t)row * N + col) = w0;
                float2 w1; w1.x = o2; w1.y = o3;
                *reinterpret_cast<float2*>(Cf + (size_t)(row + 8) * N + col) = w1;
            }
        }
    }
#undef ISSUE
#undef LD32
}

// ---------------------------------------------------------------------------
// Launch: graph fork/join. Main stream runs 4 pool chunks; side stream runs
// convert then per-chunk G1+G2 gated by events -> GEMMs overlap later pool
// chunks. Host-side stream/events created once (first, uncaptured call);
// identical launch sequence every call (deterministic, no device allocs).
// ---------------------------------------------------------------------------
struct LaunchRes {
    cudaStream_t s2;
    cudaEvent_t fork, join, p[NCHUNK];
};

extern "C" void kernel_launch(void* const* d_in, const int* in_sizes, int n_in,
                              void* d_out, int out_size)
{
    static LaunchRes R = [] {
        LaunchRes r;
        cudaStreamCreateWithFlags(&r.s2, cudaStreamNonBlocking);
        cudaEventCreateWithFlags(&r.fork, cudaEventDisableTiming);
        cudaEventCreateWithFlags(&r.join, cudaEventDisableTiming);
        for (int i = 0; i < NCHUNK; i++)
            cudaEventCreateWithFlags(&r.p[i], cudaEventDisableTiming);
        return r;
    }();

    const float* token_embeds = (const float*)d_in[0];
    const int*   attn_mask    = (const int*)  d_in[1];
    const float* W1           = (const float*)d_in[2];
    const float* b1           = (const float*)d_in[3];
    const float* W2           = (const float*)d_in[4];
    const float* b2           = (const float*)d_in[5];
    float*       out          = (float*)d_out;

    void *p_ph, *p_pl, *p_hh, *p_hl, *p_w1h, *p_w1l, *p_w2h, *p_w2l;
    cudaGetSymbolAddress(&p_ph,  g_pool_hi);
    cudaGetSymbolAddress(&p_pl,  g_pool_lo);
    cudaGetSymbolAddress(&p_hh,  g_hid_hi);
    cudaGetSymbolAddress(&p_hl,  g_hid_lo);
    cudaGetSymbolAddress(&p_w1h, g_w1t_hi);
    cudaGetSymbolAddress(&p_w1l, g_w1t_lo);
    cudaGetSymbolAddress(&p_w2h, g_w2t_hi);
    cudaGetSymbolAddress(&p_w2l, g_w2t_lo);

    cudaFuncSetAttribute(gemm_pipe<true>,
                         cudaFuncAttributeMaxDynamicSharedMemorySize, GEMM_SMEM);
    cudaFuncSetAttribute(gemm_pipe<false>,
                         cudaFuncAttributeMaxDynamicSharedMemorySize, GEMM_SMEM);

    // Fork side stream off the main (capture) stream.
    cudaEventRecord(R.fork, 0);
    cudaStreamWaitEvent(R.s2, R.fork, 0);

    // Side stream: weight convert first (overlaps pool chunk 0).
    dim3 cgrid(DIM / 32, DIM / 32, 2);
    convert_w_kernel<<<cgrid, dim3(32, 8), 0, R.s2>>>(W1, W2);

    // Main stream: 4 pool chunks, each signals an event.
    for (int c = 0; c < NCHUNK; c++) {
        pool_kernel<<<CHUNK_B, 384, 0, 0>>>(token_embeds, attn_mask, c * CHUNK_B);
        cudaEventRecord(R.p[c], 0);
    }

    // Side stream: per-chunk G1 then G2 (48 CTAs each), gated on pool chunk.
    dim3 ggrid(DIM / 64, CHUNK_B / 64);   // (12, 4)
    for (int c = 0; c < NCHUNK; c++) {
        cudaStreamWaitEvent(R.s2, R.p[c], 0);
        gemm_pipe<true><<<ggrid, 128, GEMM_SMEM, R.s2>>>(
            (const __nv_bfloat16*)p_ph, (const __nv_bfloat16*)p_pl,
            (const __nv_bfloat16*)p_w1h, (const __nv_bfloat16*)p_w1l,
            b1, nullptr, (uint32_t*)p_hh, (uint32_t*)p_hl,
            c * CHUNK_B, DIM, DIM);
        gemm_pipe<false><<<ggrid, 128, GEMM_SMEM, R.s2>>>(
            (const __nv_bfloat16*)p_hh, (const __nv_bfloat16*)p_hl,
            (const __nv_bfloat16*)p_w2h, (const __nv_bfloat16*)p_w2l,
            b2, out, nullptr, nullptr,
            c * CHUNK_B, DIM, DIM);
    }

    // Join side stream back into the main stream.
    cudaEventRecord(R.join, R.s2);
    cudaStreamWaitEvent(0, R.join, 0);
}

// round 14
// speedup vs baseline: 1.5142x; 1.5142x over previous
#include <cuda_runtime.h>
#include <cuda_bf16.h>
#include <math.h>
#include <stdint.h>

// Problem dims (fixed by the dataset)
#define BATCH 1024
#define SEQ   512
#define DIM   768

#define NMB 16
#define NNB 12
#define NCONV_PER_W 144
#define NCONV (2 * NCONV_PER_W)      // 288
#define ID_G1 NCONV                  // 288
#define ID_G2 (ID_G1 + NMB * NNB)    // 480
#define NTILES (ID_G2 + NMB * NNB)   // 672
#define NPERS 148                    // persistent CTAs (1/SM)

// ---------------------------------------------------------------------------
// Scratch + flags (allocation-free rule: __device__ globals)
// ---------------------------------------------------------------------------
__device__ uint32_t g_pool_hi[BATCH * DIM / 2];
__device__ uint32_t g_pool_lo[BATCH * DIM / 2];
__device__ uint32_t g_hid_hi[BATCH * DIM / 2];
__device__ uint32_t g_hid_lo[BATCH * DIM / 2];
__device__ __nv_bfloat16 g_w1t_hi[DIM * DIM];   // [N][K]
__device__ __nv_bfloat16 g_w1t_lo[DIM * DIM];
__device__ __nv_bfloat16 g_w2t_hi[DIM * DIM];
__device__ __nv_bfloat16 g_w2t_lo[DIM * DIM];

// Flags: monotonic within a launch; each reset by its LAST consumer ->
// all-zero at entry and exit of every execution (graph-replay safe; protocol
// validated in R11 which passed correctness).
__device__ int g_w1done, g_dw1;   // conv W1 done (144) / G1 tiles done (192)
__device__ int g_w2done, g_dw2;   // conv W2 done (144) / G2 tiles done (192)
__device__ int g_c2[NMB];         // G1 tiles done per mb (12)
__device__ int g_d2[NMB];         // G2 tiles done per mb (12) -> resets c2

__device__ __forceinline__ int ld_acq(const int* p)
{
    int v;
    asm volatile("ld.acquire.gpu.s32 %0, [%1];" : "=r"(v) : "l"(p) : "memory");
    return v;
}

__device__ __forceinline__ void split1(float x, float& h, float& l)
{
    __nv_bfloat16 hb = __float2bfloat16(x);
    h = __bfloat162float(hb);
    l = x - h;
}

__device__ __forceinline__ uint32_t pack_bf2(float a, float b)
{
    __nv_bfloat162 t = __floats2bfloat162_rn(a, b);   // .x = a (low 16 bits)
    return *reinterpret_cast<uint32_t*>(&t);
}

__device__ __forceinline__ float2 ldcs_f2(const float2* p)
{
    float2 v;
    asm volatile("ld.global.cs.v2.f32 {%0,%1}, [%2];"
                 : "=f"(v.x), "=f"(v.y) : "l"(p));
    return v;
}

// ---------------------------------------------------------------------------
// Kernel 1: masked sum pooling (R9 verbatim; 83% DRAM = roofline)
// ---------------------------------------------------------------------------
__global__ __launch_bounds__(384) void pool_kernel(
    const float* __restrict__ x,      // [BATCH, SEQ, DIM]
    const int*   __restrict__ mask)   // [BATCH, SEQ]
{
    __shared__ int s_idx[SEQ];
    __shared__ int s_cnt;

    const int b   = blockIdx.x;
    const int tid = threadIdx.x;

    if (tid == 0) s_cnt = 0;
    __syncthreads();

    const int* mrow = mask + (size_t)b * SEQ;
    for (int s = tid; s < SEQ; s += 384) {
        if (mrow[s] != 0) {
            int p = atomicAdd(&s_cnt, 1);
            s_idx[p] = s;
        }
    }
    __syncthreads();

    const int cnt = s_cnt;
    const float2* base = reinterpret_cast<const float2*>(x + (size_t)b * SEQ * DIM);
    const int rs2 = DIM / 2;

    float2 acc; acc.x = 0.f; acc.y = 0.f;

    int i = 0;
    for (; i + 4 <= cnt; i += 4) {
        int s0 = s_idx[i + 0];
        int s1 = s_idx[i + 1];
        int s2 = s_idx[i + 2];
        int s3 = s_idx[i + 3];
        float2 v0 = ldcs_f2(base + (size_t)s0 * rs2 + tid);
        float2 v1 = ldcs_f2(base + (size_t)s1 * rs2 + tid);
        float2 v2 = ldcs_f2(base + (size_t)s2 * rs2 + tid);
        float2 v3 = ldcs_f2(base + (size_t)s3 * rs2 + tid);
        acc.x += (v0.x + v1.x) + (v2.x + v3.x);
        acc.y += (v0.y + v1.y) + (v2.y + v3.y);
    }
    for (; i < cnt; i++) {
        float2 v = ldcs_f2(base + (size_t)s_idx[i] * rs2 + tid);
        acc.x += v.x;
        acc.y += v.y;
    }

    float hx, lx, hy, ly;
    split1(acc.x, hx, lx);
    split1(acc.y, hy, ly);
    g_pool_hi[(size_t)b * rs2 + tid] = pack_bf2(hx, hy);
    g_pool_lo[(size_t)b * rs2 + tid] = pack_bf2(lx, ly);
}

// ---------------------------------------------------------------------------
// GEMM tile core (R9 gemm_pipe body, measured 26.6us/192 tiles):
// C = tanh(A @ B^T + bias); A [M][K], B [N][K] bf16 hi/lo; HH+HL+LH split;
// cp.async 3-stage pipeline; 64x64 tile, BK=32; 128 threads (2x2 warps).
// ---------------------------------------------------------------------------
#define SROW 80
#define TILE_B (64 * SROW)            // 5120 B
#define STAGE_B (4 * TILE_B)          // 20480 B
#define NSTAGES 3
#define GEMM_SMEM (NSTAGES * STAGE_B) // 61440 B (>= conv's 16.6KB)
#define OFF_AH 0
#define OFF_AL TILE_B
#define OFF_BH (2 * TILE_B)
#define OFF_BL (3 * TILE_B)

__device__ __forceinline__ void cp16(uint32_t dst, const void* src)
{
    asm volatile("cp.async.cg.shared.global [%0], [%1], 16;"
                 :: "r"(dst), "l"(src));
}
#define CP_COMMIT() asm volatile("cp.async.commit_group;" ::: "memory")
#define CP_WAIT2()  asm volatile("cp.async.wait_group 2;" ::: "memory")

__device__ __forceinline__ void mma_bf16(
    float c[4], uint32_t a0, uint32_t a1, uint32_t a2, uint32_t a3,
    uint32_t b0, uint32_t b1)
{
    asm volatile(
        "mma.sync.aligned.m16n8k16.row.col.f32.bf16.bf16.f32 "
        "{%0,%1,%2,%3}, {%4,%5,%6,%7}, {%8,%9}, {%0,%1,%2,%3};\n"
        : "+f"(c[0]), "+f"(c[1]), "+f"(c[2]), "+f"(c[3])
        : "r"(a0), "r"(a1), "r"(a2), "r"(a3), "r"(b0), "r"(b1));
}

template <bool SPLIT_OUT>
__device__ void gemm_tile(
    char* dyn, int m0, int n0,
    const __nv_bfloat16* __restrict__ Ah, const __nv_bfloat16* __restrict__ Al,
    const __nv_bfloat16* __restrict__ Bh, const __nv_bfloat16* __restrict__ Bl,
    const float* __restrict__ bias,
    float* __restrict__ Cf, uint32_t* __restrict__ Chh, uint32_t* __restrict__ Chl)
{
    const uint32_t sbase = (uint32_t)__cvta_generic_to_shared(dyn);
    const int K = DIM, N = DIM;

    const int tid  = threadIdx.x;
    const int lane = tid & 31;
    const int warp = tid >> 5;       // 0..3
    const int gid  = lane >> 2;
    const int tig  = lane & 3;
    const int warpM = (warp & 1) * 32;
    const int warpN = (warp >> 1) * 32;

    const int r0 = tid >> 2;          // 0..31
    const int q0 = tid & 3;           // 16B k-group

    float acc[2][4][4];
#pragma unroll
    for (int mt = 0; mt < 2; mt++)
#pragma unroll
        for (int nt = 0; nt < 4; nt++)
#pragma unroll
            for (int r = 0; r < 4; r++)
                acc[mt][nt][r] = 0.f;

#define ISSUE(k0v, st)                                                         \
    do {                                                                       \
        uint32_t sb = sbase + (st) * STAGE_B;                                  \
        _Pragma("unroll")                                                      \
        for (int l = 0; l < 2; l++) {                                          \
            int row = r0 + 32 * l;                                             \
            uint32_t d = sb + row * SROW + q0 * 16;                            \
            size_t ga = (size_t)(m0 + row) * K + (k0v) + q0 * 8;               \
            size_t gb = (size_t)(n0 + row) * K + (k0v) + q0 * 8;               \
            cp16(d + OFF_AH, Ah + ga);                                         \
            cp16(d + OFF_AL, Al + ga);                                         \
            cp16(d + OFF_BH, Bh + gb);                                         \
            cp16(d + OFF_BL, Bl + gb);                                         \
        }                                                                      \
        CP_COMMIT();                                                           \
    } while (0)

#define LD32(off) (*reinterpret_cast<const uint32_t*>(dyn + (off)))

    ISSUE(0, 0);
    ISSUE(32, 1);
    ISSUE(64, 2);

    const int NIT = K / 32;   // 24
    for (int t = 0; t < NIT; t++) {
        CP_WAIT2();
        __syncthreads();

        const uint32_t sb = (uint32_t)((t % NSTAGES) * STAGE_B);
#pragma unroll
        for (int ks = 0; ks < 2; ks++) {
            const int kb = ks * 8;

            uint32_t ah[2][4], al[2][4];
#pragma unroll
            for (int mt = 0; mt < 2; mt++) {
                const int rm = warpM + mt * 16 + gid;
                uint32_t b0 = sb + rm * SROW + (kb + tig) * 4;
                uint32_t b8 = sb + (rm + 8) * SROW + (kb + tig) * 4;
                ah[mt][0] = LD32(b0 + OFF_AH);
                ah[mt][1] = LD32(b8 + OFF_AH);
                ah[mt][2] = LD32(b0 + OFF_AH + 16);
                ah[mt][3] = LD32(b8 + OFF_AH + 16);
                al[mt][0] = LD32(b0 + OFF_AL);
                al[mt][1] = LD32(b8 + OFF_AL);
                al[mt][2] = LD32(b0 + OFF_AL + 16);
                al[mt][3] = LD32(b8 + OFF_AL + 16);
            }
            uint32_t bh[4][2], bl[4][2];
#pragma unroll
            for (int nt = 0; nt < 4; nt++) {
                const int nn = warpN + nt * 8 + gid;
                uint32_t b0 = sb + nn * SROW + (kb + tig) * 4;
                bh[nt][0] = LD32(b0 + OFF_BH);
                bh[nt][1] = LD32(b0 + OFF_BH + 16);
                bl[nt][0] = LD32(b0 + OFF_BL);
                bl[nt][1] = LD32(b0 + OFF_BL + 16);
            }

#pragma unroll
            for (int mt = 0; mt < 2; mt++)
#pragma unroll
                for (int nt = 0; nt < 4; nt++) {
                    mma_bf16(acc[mt][nt], ah[mt][0], ah[mt][1], ah[mt][2], ah[mt][3],
                             bh[nt][0], bh[nt][1]);
                    mma_bf16(acc[mt][nt], ah[mt][0], ah[mt][1], ah[mt][2], ah[mt][3],
                             bl[nt][0], bl[nt][1]);
                    mma_bf16(acc[mt][nt], al[mt][0], al[mt][1], al[mt][2], al[mt][3],
                             bh[nt][0], bh[nt][1]);
                }
        }
        __syncthreads();

        if (t + NSTAGES < NIT) ISSUE((t + NSTAGES) * 32, t % NSTAGES);
        else                   CP_COMMIT();   // keep group count uniform
    }

#pragma unroll
    for (int mt = 0; mt < 2; mt++) {
#pragma unroll
        for (int nt = 0; nt < 4; nt++) {
            const int row = m0 + warpM + mt * 16 + gid;
            const int col = n0 + warpN + nt * 8 + tig * 2;
            float2 bv = *reinterpret_cast<const float2*>(bias + col);
            float o0 = tanhf(acc[mt][nt][0] + bv.x);
            float o1 = tanhf(acc[mt][nt][1] + bv.y);
            float o2 = tanhf(acc[mt][nt][2] + bv.x);
            float o3 = tanhf(acc[mt][nt][3] + bv.y);
            if (SPLIT_OUT) {
                float h0, l0, h1, l1;
                split1(o0, h0, l0);
                split1(o1, h1, l1);
                size_t idx = ((size_t)row * N + col) >> 1;
                Chh[idx] = pack_bf2(h0, h1);
                Chl[idx] = pack_bf2(l0, l1);
                split1(o2, h0, l0);
                split1(o3, h1, l1);
                size_t idx2 = ((size_t)(row + 8) * N + col) >> 1;
                Chh[idx2] = pack_bf2(h0, h1);
                Chl[idx2] = pack_bf2(l0, l1);
            } else {
                float2 w0; w0.x = o0; w0.y = o1;
                *reinterpret_cast<float2*>(Cf + (size_t)row * N + col) = w0;
                float2 w1; w1.x = o2; w1.y = o3;
                *reinterpret_cast<float2*>(Cf + (size_t)(row + 8) * N + col) = w1;
            }
        }
    }
#undef ISSUE
#undef LD32
}

// ---------------------------------------------------------------------------
// Persistent kernel: 148 CTAs, static round-robin over 672 tiles
// (288 conv | 192 G1 | 192 G2, mb-major). Flags gate G1 on conv, G2 on G1.
// ---------------------------------------------------------------------------
__global__ __launch_bounds__(128) void fused_gemms(
    const float* __restrict__ W1, const float* __restrict__ b1,
    const float* __restrict__ W2, const float* __restrict__ b2,
    float* __restrict__ out)
{
    extern __shared__ char dyn[];
    const int bid = blockIdx.x;
    const int tid = threadIdx.x;

    for (int id = bid; id < NTILES; id += NPERS) {
        if (id < NCONV) {
            // ----- conv tile: 64x64 transpose + bf16 hi/lo split -----
            const int wz = id / NCONV_PER_W;
            const int t  = id % NCONV_PER_W;
            const int n0 = (t % 12) * 64;
            const int k0 = (t / 12) * 64;
            const float* W = wz ? W2 : W1;
            __nv_bfloat16* Oh = wz ? g_w2t_hi : g_w1t_hi;
            __nv_bfloat16* Ol = wz ? g_w2t_lo : g_w1t_lo;

            float* s = reinterpret_cast<float*>(dyn);   // [64][65] = 16.6KB
            const int cc = tid & 63;
            const int rr = tid >> 6;   // 0..1
#pragma unroll
            for (int i = 0; i < 32; i++) {
                int r = rr + 2 * i;    // k row
                s[cc * 65 + r] = W[(size_t)(k0 + r) * DIM + n0 + cc];
            }
            __syncthreads();
#pragma unroll
            for (int i = 0; i < 32; i++) {
                int nl = rr + 2 * i;   // local n
                float v = s[nl * 65 + cc];   // = W[k0+cc][n0+nl]
                float h, l;
                split1(v, h, l);
                size_t o = (size_t)(n0 + nl) * DIM + k0 + cc;
                Oh[o] = __float2bfloat16(h);
                Ol[o] = __float2bfloat16(l);
            }
            __syncthreads();
            if (tid == 0) {
                __threadfence();
                atomicAdd(wz ? &g_w2done : &g_w1done, 1);
            }
            __syncthreads();
        } else if (id < ID_G2) {
            // ----- G1 tile: hidden = tanh(pooled @ W1 + b1) -----
            const int t = id - ID_G1;
            const int mb = t / NNB, nb = t % NNB;
            if (tid == 0)
                while (ld_acq(&g_w1done) < NCONV_PER_W) __nanosleep(128);
            __syncthreads();

            gemm_tile<true>(dyn, mb * 64, nb * 64,
                            (const __nv_bfloat16*)g_pool_hi,
                            (const __nv_bfloat16*)g_pool_lo,
                            g_w1t_hi, g_w1t_lo, b1,
                            nullptr, g_hid_hi, g_hid_lo);

            __syncthreads();
            if (tid == 0) {
                __threadfence();
                atomicAdd(&g_c2[mb], 1);
                if (atomicAdd(&g_dw1, 1) == NMB * NNB - 1) {
                    atomicExch(&g_w1done, 0);
                    atomicExch(&g_dw1, 0);
                }
            }
            __syncthreads();
        } else {
            // ----- G2 tile: out = tanh(hidden @ W2 + b2) -----
            const int t = id - ID_G2;
            const int mb = t / NNB, nb = t % NNB;
            if (tid == 0) {
                while (ld_acq(&g_w2done) < NCONV_PER_W) __nanosleep(128);
                while (ld_acq(&g_c2[mb]) < NNB)         __nanosleep(128);
            }
            __syncthreads();

            gemm_tile<false>(dyn, mb * 64, nb * 64,
                             (const __nv_bfloat16*)g_hid_hi,
                             (const __nv_bfloat16*)g_hid_lo,
                             g_w2t_hi, g_w2t_lo, b2,
                             out, nullptr, nullptr);

            __syncthreads();
            if (tid == 0) {
                if (atomicAdd(&g_d2[mb], 1) == NNB - 1) {
                    atomicExch(&g_c2[mb], 0);
                    atomicExch(&g_d2[mb], 0);
                }
                if (atomicAdd(&g_dw2, 1) == NMB * NNB - 1) {
                    atomicExch(&g_w2done, 0);
                    atomicExch(&g_dw2, 0);
                }
            }
            __syncthreads();
        }
    }
}

// ---------------------------------------------------------------------------
// Launch: pool, then the persistent fused GEMM kernel. Two launches.
// ---------------------------------------------------------------------------
extern "C" void kernel_launch(void* const* d_in, const int* in_sizes, int n_in,
                              void* d_out, int out_size)
{
    const float* token_embeds = (const float*)d_in[0];
    const int*   attn_mask    = (const int*)  d_in[1];
    const float* W1           = (const float*)d_in[2];
    const float* b1           = (const float*)d_in[3];
    const float* W2           = (const float*)d_in[4];
    const float* b2           = (const float*)d_in[5];
    float*       out          = (float*)d_out;

    cudaFuncSetAttribute(fused_gemms,
                         cudaFuncAttributeMaxDynamicSharedMemorySize, GEMM_SMEM);

    pool_kernel<<<BATCH, 384>>>(token_embeds, attn_mask);
    fused_gemms<<<NPERS, 128, GEMM_SMEM>>>(W1, b1, W2, b2, out);
}